// round 11
// baseline (speedup 1.0000x reference)
#include <cuda_runtime.h>
#include <cuda.h>
#include <cstdint>

// CapsuleLayer dynamic routing — persistent CTAs (grid=148), flat TMA
// stream, depth-3 pipeline, prefetched x, packed f32x2 FMA.
// x: [B=256, N=1152, CI=8] f32, w: [C=10, N=1152, CI=8, CO=16] f32
// out: [C, B, 1, 1, 16] f32

#define Cc 10
#define Bb 256
#define Nn 1152
#define NTHREADS 576
#define NWARPS 18
#define RPB 144
#define NBUF 3
#define NUNITS_TOTAL 1280
#define GRID 148
#define COLW  18432              // bytes per 128B-column box (144*128)
#define BUFB  (4*COLW)           // 73728 bytes per buffer
#define MBAR_OFF (NBUF*BUFB)     // 221184
#define WRED_OFF (MBAR_OFF + 64)
#define SRED_OFF (WRED_OFF + NWARPS*2*16*4)
#define OUTV_OFF (SRED_OFF + NWARPS*2*4)   // 223696: 16B aligned
#define SMEM_BYTES (OUTV_OFF + 2*16*4)

__device__ __forceinline__ void mbar_init(uint32_t a, uint32_t cnt) {
    asm volatile("mbarrier.init.shared.b64 [%0], %1;" :: "r"(a), "r"(cnt) : "memory");
}
__device__ __forceinline__ void mbar_expect_tx(uint32_t a, uint32_t bytes) {
    asm volatile("mbarrier.arrive.expect_tx.shared.b64 _, [%0], %1;"
                 :: "r"(a), "r"(bytes) : "memory");
}
__device__ __forceinline__ void mbar_wait(uint32_t a, uint32_t parity) {
    asm volatile(
        "{\n\t.reg .pred P1;\n\t"
        "W_%=:\n\t"
        "mbarrier.try_wait.parity.acquire.cta.shared::cta.b64 P1, [%0], %1, 0x989680;\n\t"
        "@P1 bra.uni D_%=;\n\t"
        "bra.uni W_%=;\n\t"
        "D_%=:\n\t}"
        :: "r"(a), "r"(parity) : "memory");
}
__device__ __forceinline__ void tma2d(uint32_t dst, const CUtensorMap* m,
                                      int cx, int cy, uint32_t mb) {
    asm volatile(
        "cp.async.bulk.tensor.2d.shared::cta.global.tile.mbarrier::complete_tx::bytes "
        "[%0], [%1, {%2, %3}], [%4];"
        :: "r"(dst), "l"(m), "r"(cx), "r"(cy), "r"(mb) : "memory");
}

// packed f32x2 helpers
__device__ __forceinline__ void ffma2(unsigned long long& d,
                                      unsigned long long a,
                                      unsigned long long b) {
    asm("fma.rn.f32x2 %0, %1, %2, %0;" : "+l"(d) : "l"(a), "l"(b));
}
__device__ __forceinline__ void fadd2(unsigned long long& d, unsigned long long a) {
    asm("add.rn.f32x2 %0, %0, %1;" : "+l"(d) : "l"(a));
}
__device__ __forceinline__ unsigned long long bcast2(float v) {
    unsigned long long r;
    asm("mov.b64 %0, {%1, %1};" : "=l"(r) : "f"(v));
    return r;
}
__device__ __forceinline__ float plo(unsigned long long v) {
    return __uint_as_float((unsigned)v);
}
__device__ __forceinline__ float phi(unsigned long long v) {
    return __uint_as_float((unsigned)(v >> 32));
}

__global__ __launch_bounds__(NTHREADS, 1)
void capsule_kernel(const __grid_constant__ CUtensorMap tmap,
                    const float* __restrict__ x,
                    float* __restrict__ out)
{
    extern __shared__ char smc[];
    float* wred = (float*)(smc + WRED_OFF);    // [18][2][16]
    float* sred = (float*)(smc + SRED_OFF);    // [18][2]
    float* outv = (float*)(smc + OUTV_OFF);    // [2][16], 16B aligned

    const int tid  = threadIdx.x;
    const int g    = tid & 1;               // which b of pair
    const int oh   = (tid >> 1) & 1;        // which CO half
    const int rw   = tid >> 2;              // row within block, 0..143
    const int lane = tid & 31;
    const int wid  = tid >> 5;
    const int bid  = blockIdx.x;

    const int nunits = (NUNITS_TOTAL - bid + GRID - 1) / GRID;
    const int qtot   = nunits * 8;

    const uint32_t sbase = (uint32_t)__cvta_generic_to_shared(smc);
    const uint32_t mb0 = sbase + MBAR_OFF;

    auto stage = [&](int q) {               // tid 0 only
        const int i = q >> 3, s = q & 7;
        const int u = bid + i * GRID;
        const int cy = (u % Cc) * Nn + s * RPB;
        const int bi = q % NBUF;
        const uint32_t dstb = sbase + (uint32_t)(bi * BUFB);
        mbar_expect_tx(mb0 + bi * 8, BUFB);
        #pragma unroll
        for (int j = 0; j < 4; ++j)
            tma2d(dstb + j * COLW, &tmap, j * 32, cy, mb0 + bi * 8);
    };

    if (tid == 0) {
        mbar_init(mb0 + 0, 1);
        mbar_init(mb0 + 8, 1);
        mbar_init(mb0 + 16, 1);
    }
    __syncthreads();
    if (tid == 0) { stage(0); stage(1); stage(2); }

    unsigned long long Pp[8][4];            // packed priors: pair j = outputs (2j,2j+1)
    const int r7  = rw & 7;
    const int oh2 = oh * 2;
    const uint32_t rowoff = (uint32_t)rw * 128;

    // initial x prefetch: unit 0, block 0
    float4 nxa, nxb;
    {
        const int b0 = (bid / Cc) * 2 + g;
        const float* xp = x + ((size_t)b0 * Nn + rw) * 8;
        nxa = *(const float4*)xp;
        nxb = *(const float4*)(xp + 4);
    }

    for (int i = 0; i < nunits; ++i) {
        const int u = bid + i * GRID;
        const int c = u % Cc;
        const int bbase = (u / Cc) * 2;

        // ======== Phase 1: 8 blocks of this unit -> Pp[8][4] ========
        #pragma unroll
        for (int s = 0; s < 8; ++s) {
            const int q  = i * 8 + s;
            const int bi = q % NBUF;

            const float4 xa = nxa, xb = nxb;

            // prefetch next block's x BEFORE the barrier wait
            {
                int i2 = i, s2 = s + 1;
                if (s2 == 8) { s2 = 0; i2 = (i + 1 < nunits) ? i + 1 : i; }
                const int u2 = bid + i2 * GRID;
                const int b2 = (u2 / Cc) * 2 + g;
                const float* xp = x + ((size_t)b2 * Nn + s2 * RPB + rw) * 8;
                nxa = *(const float4*)xp;
                nxb = *(const float4*)(xp + 4);
            }

            mbar_wait(mb0 + bi * 8, (q / NBUF) & 1);

            const float xv[8] = {xa.x, xa.y, xa.z, xa.w, xb.x, xb.y, xb.z, xb.w};
            #pragma unroll
            for (int j = 0; j < 4; ++j) Pp[s][j] = 0ull;

            const char* bufp = smc + (size_t)bi * BUFB + rowoff;
            #pragma unroll
            for (int ii = 0; ii < 8; ++ii) {
                const unsigned long long ax = bcast2(xv[ii]);
                #pragma unroll
                for (int m = 0; m < 2; ++m) {
                    const int C = ii * 4 + m;                // 16B unit (oh=0 base)
                    const uint32_t uu = (uint32_t)((C & 7) + oh2);
                    const uint32_t off = (uint32_t)((C >> 3) * COLW)
                                       + ((uu ^ (uint32_t)r7) << 4);
                    const ulonglong2 wv = *(const ulonglong2*)(bufp + off);
                    ffma2(Pp[s][m*2+0], ax, wv.x);
                    ffma2(Pp[s][m*2+1], ax, wv.y);
                }
            }

            __syncthreads();                 // all done reading buffer bi
            if (tid == 0 && q + NBUF < qtot) stage(q + NBUF);
        }

        // ======== Phase 2: routing for this unit ========
        float Lr[8];

        // ---- iteration 0: s = mean_n priors ----
        {
            unsigned long long a2[4];
            #pragma unroll
            for (int j = 0; j < 4; ++j) {
                unsigned long long v = Pp[0][j];
                #pragma unroll
                for (int k = 1; k < 8; ++k) fadd2(v, Pp[k][j]);
                a2[j] = v;
            }
            #pragma unroll
            for (int off = 4; off <= 16; off <<= 1)
                #pragma unroll
                for (int j = 0; j < 4; ++j) {
                    unsigned long long t = __shfl_xor_sync(0xffffffffu, a2[j], off);
                    fadd2(a2[j], t);
                }
            if (lane < 4) {
                #pragma unroll
                for (int j = 0; j < 4; ++j) {
                    wred[(wid*2+g)*16 + oh*8 + 2*j]     = plo(a2[j]);
                    wred[(wid*2+g)*16 + oh*8 + 2*j + 1] = phi(a2[j]);
                }
            }
            __syncthreads();
            if (tid < 32) {
                const int g2 = tid & 1, o2 = tid >> 1;
                float sv = 0.f;
                #pragma unroll
                for (int wi = 0; wi < NWARPS; ++wi)
                    sv += wred[(wi*2+g2)*16 + o2];
                sv *= (1.0f / Nn);
                float sq = sv * sv;
                #pragma unroll
                for (int off = 2; off <= 16; off <<= 1)
                    sq += __shfl_xor_sync(0xffffffffu, sq, off);
                const float coef = sq / (1.f + sq) * rsqrtf(sq);
                outv[g2*16 + o2] = sv * coef;
            }
            __syncthreads();
        }

        // ---- iterations 1 and 2 ----
        #pragma unroll
        for (int it = 1; it < 3; ++it) {
            unsigned long long ov2[4];
            {
                const ulonglong2* op = (const ulonglong2*)(outv + g*16 + oh*8);
                const ulonglong2 t0 = op[0], t1 = op[1];
                ov2[0] = t0.x; ov2[1] = t0.y; ov2[2] = t1.x; ov2[3] = t1.y;
            }

            float lmax = -1e30f;
            #pragma unroll
            for (int k = 0; k < 8; ++k) {
                unsigned long long d2 = 0ull;
                #pragma unroll
                for (int j = 0; j < 4; ++j) ffma2(d2, Pp[k][j], ov2[j]);
                float dot = plo(d2) + phi(d2);
                dot += __shfl_xor_sync(0xffffffffu, dot, 2);   // join o-halves
                const float L = (it == 1) ? dot : (Lr[k] + dot);
                Lr[k] = L;
                lmax = fmaxf(lmax, L);
            }
            #pragma unroll
            for (int off = 4; off <= 16; off <<= 1)
                lmax = fmaxf(lmax, __shfl_xor_sync(0xffffffffu, lmax, off));
            __syncthreads();                 // previous sred consumers done
            if (lane < 2) sred[wid*2 + g] = lmax;
            __syncthreads();
            float M = -1e30f;
            #pragma unroll
            for (int wi = 0; wi < NWARPS; ++wi)
                M = fmaxf(M, sred[wi*2 + g]);

            float e[8], lsum = 0.f;
            #pragma unroll
            for (int k = 0; k < 8; ++k) {
                e[k] = __expf(Lr[k] - M);
                lsum += e[k];
            }
            #pragma unroll
            for (int off = 4; off <= 16; off <<= 1)
                lsum += __shfl_xor_sync(0xffffffffu, lsum, off);
            __syncthreads();                 // all M reads done
            if (lane < 2) sred[wid*2 + g] = lsum;
            __syncthreads();
            float Z = 0.f;
            #pragma unroll
            for (int wi = 0; wi < NWARPS; ++wi)
                Z += sred[wi*2 + g];

            unsigned long long a2[4] = {0ull, 0ull, 0ull, 0ull};
            #pragma unroll
            for (int k = 0; k < 8; ++k) {
                const unsigned long long ek = bcast2(e[k]);
                #pragma unroll
                for (int j = 0; j < 4; ++j) ffma2(a2[j], ek, Pp[k][j]);
            }
            #pragma unroll
            for (int off = 4; off <= 16; off <<= 1)
                #pragma unroll
                for (int j = 0; j < 4; ++j) {
                    unsigned long long t = __shfl_xor_sync(0xffffffffu, a2[j], off);
                    fadd2(a2[j], t);
                }
            if (lane < 4) {
                #pragma unroll
                for (int j = 0; j < 4; ++j) {
                    wred[(wid*2+g)*16 + oh*8 + 2*j]     = plo(a2[j]);
                    wred[(wid*2+g)*16 + oh*8 + 2*j + 1] = phi(a2[j]);
                }
            }
            __syncthreads();
            if (tid < 32) {
                const int g2 = tid & 1, o2 = tid >> 1;
                float sv = 0.f;
                #pragma unroll
                for (int wi = 0; wi < NWARPS; ++wi)
                    sv += wred[(wi*2+g2)*16 + o2];
                sv /= Z;
                float sq = sv * sv;
                #pragma unroll
                for (int off = 2; off <= 16; off <<= 1)
                    sq += __shfl_xor_sync(0xffffffffu, sq, off);
                const float coef = sq / (1.f + sq) * rsqrtf(sq);
                outv[g2*16 + o2] = sv * coef;
            }
            __syncthreads();
        }

        // ======== output for this unit: [C, B, 1, 1, 16] ========
        if (tid < 32) {
            const int g2 = tid & 1, o2 = tid >> 1;
            out[((size_t)c * Bb + bbase + g2) * 16 + o2] = outv[g2*16 + o2];
        }
        __syncthreads();                     // outv stable before next unit
    }
}

// ---------------- host ----------------
typedef CUresult (*EncodeTiledFn)(
    CUtensorMap*, CUtensorMapDataType, cuuint32_t, void*,
    const cuuint64_t*, const cuuint64_t*, const cuuint32_t*, const cuuint32_t*,
    CUtensorMapInterleave, CUtensorMapSwizzle, CUtensorMapL2promotion,
    CUtensorMapFloatOOBfill);

extern "C" void kernel_launch(void* const* d_in, const int* in_sizes, int n_in,
                              void* d_out, int out_size)
{
    const float* x = (const float*)d_in[0];
    void* w = (void*)d_in[1];
    float* out = (float*)d_out;

    EncodeTiledFn encode = nullptr;
    cudaDriverEntryPointQueryResult qr;
    cudaGetDriverEntryPoint("cuTensorMapEncodeTiled", (void**)&encode,
                            cudaEnableDefault, &qr);

    CUtensorMap tmap;
    cuuint64_t dims[2]    = { 128, (cuuint64_t)Cc * Nn };
    cuuint64_t strides[1] = { 128 * 4 };
    cuuint32_t box[2]     = { 32, RPB };
    cuuint32_t estr[2]    = { 1, 1 };
    encode(&tmap, CU_TENSOR_MAP_DATA_TYPE_FLOAT32, 2, w,
           dims, strides, box, estr,
           CU_TENSOR_MAP_INTERLEAVE_NONE, CU_TENSOR_MAP_SWIZZLE_128B,
           CU_TENSOR_MAP_L2_PROMOTION_L2_128B,
           CU_TENSOR_MAP_FLOAT_OOB_FILL_NONE);

    cudaFuncSetAttribute(capsule_kernel,
                         cudaFuncAttributeMaxDynamicSharedMemorySize, SMEM_BYTES);

    capsule_kernel<<<GRID, NTHREADS, SMEM_BYTES>>>(tmap, x, out);
}

// round 12
// speedup vs baseline: 1.1152x; 1.1152x over previous
#include <cuda_runtime.h>
#include <cuda.h>
#include <cstdint>

// CapsuleLayer dynamic routing — TMA (SW128) triple-buffered w staging,
// wave-based grid (1280 CTAs), prefetched x, scalar FMA (R6 structure).
// x: [B=256, N=1152, CI=8] f32, w: [C=10, N=1152, CI=8, CO=16] f32
// out: [C, B, 1, 1, 16] f32
//
// One CTA = (c, pair of b). 576 threads; g=tid&1 (which b), oh=(tid>>1)&1
// (CO half), rw=tid>>2 (row 0..143). w[c] streams in 8 blocks of 144 rows;
// each block = 4 TMA 2D loads (box 32 floats x 144 rows, SW128 swizzle)
// into 3 round-robin SMEM buffers (block q+3 always in flight). x for
// block s+1 is prefetched before the mbarrier wait of block s. Priors
// P[8][8] stay register-resident through all 3 routing iterations.

#define Cc 10
#define Bb 256
#define Nn 1152
#define NTHREADS 576
#define NWARPS 18
#define NBLKS 8
#define RPB 144
#define NBUF 3
#define COLW  18432              // bytes per 128B-column box (144*128)
#define BUFB  (4*COLW)           // 73728 bytes per buffer
#define MBAR_OFF (NBUF*BUFB)     // 221184
#define WRED_OFF (MBAR_OFF + 64)
#define SRED_OFF (WRED_OFF + NWARPS*2*16*4)
#define OUTV_OFF (SRED_OFF + NWARPS*2*4)
#define SMEM_BYTES (OUTV_OFF + 2*16*4)

__device__ __forceinline__ void mbar_init(uint32_t a, uint32_t cnt) {
    asm volatile("mbarrier.init.shared.b64 [%0], %1;" :: "r"(a), "r"(cnt) : "memory");
}
__device__ __forceinline__ void mbar_expect_tx(uint32_t a, uint32_t bytes) {
    asm volatile("mbarrier.arrive.expect_tx.shared.b64 _, [%0], %1;"
                 :: "r"(a), "r"(bytes) : "memory");
}
__device__ __forceinline__ void mbar_wait(uint32_t a, uint32_t parity) {
    asm volatile(
        "{\n\t.reg .pred P1;\n\t"
        "W_%=:\n\t"
        "mbarrier.try_wait.parity.acquire.cta.shared::cta.b64 P1, [%0], %1, 0x989680;\n\t"
        "@P1 bra.uni D_%=;\n\t"
        "bra.uni W_%=;\n\t"
        "D_%=:\n\t}"
        :: "r"(a), "r"(parity) : "memory");
}
__device__ __forceinline__ void tma2d(uint32_t dst, const CUtensorMap* m,
                                      int cx, int cy, uint32_t mb) {
    asm volatile(
        "cp.async.bulk.tensor.2d.shared::cta.global.tile.mbarrier::complete_tx::bytes "
        "[%0], [%1, {%2, %3}], [%4];"
        :: "r"(dst), "l"(m), "r"(cx), "r"(cy), "r"(mb) : "memory");
}

__global__ __launch_bounds__(NTHREADS, 1)
void capsule_kernel(const __grid_constant__ CUtensorMap tmap,
                    const float* __restrict__ x,
                    float* __restrict__ out)
{
    extern __shared__ char smc[];
    float* wred = (float*)(smc + WRED_OFF);    // [18][2][16]
    float* sred = (float*)(smc + SRED_OFF);    // [18][2]
    float* outv = (float*)(smc + OUTV_OFF);    // [2][16]

    const int tid  = threadIdx.x;
    const int g    = tid & 1;               // which b of pair
    const int oh   = (tid >> 1) & 1;        // which CO half
    const int rw   = tid >> 2;              // row within block, 0..143
    const int lane = tid & 31;
    const int wid  = tid >> 5;
    const int c    = blockIdx.x >> 7;
    const int bbase = (blockIdx.x & 127) << 1;
    const int b    = bbase + g;

    const uint32_t sbase = (uint32_t)__cvta_generic_to_shared(smc);
    const uint32_t mb0 = sbase + MBAR_OFF;

    auto stage = [&](int q) {               // tid 0 only
        const int bi = q % NBUF;
        const uint32_t dstb = sbase + (uint32_t)(bi * BUFB);
        const int cy = c * Nn + q * RPB;
        mbar_expect_tx(mb0 + bi * 8, BUFB);
        #pragma unroll
        for (int j = 0; j < 4; ++j)
            tma2d(dstb + j * COLW, &tmap, j * 32, cy, mb0 + bi * 8);
    };

    if (tid == 0) {
        mbar_init(mb0 + 0, 1);
        mbar_init(mb0 + 8, 1);
        mbar_init(mb0 + 16, 1);
    }
    __syncthreads();
    if (tid == 0) { stage(0); stage(1); stage(2); }

    float P[NBLKS][8];
    const int r7  = rw & 7;
    const int oh2 = oh * 2;
    const uint32_t rowoff = (uint32_t)rw * 128;
    const float* __restrict__ xbase = x + ((size_t)b * Nn + rw) * 8;

    // initial x prefetch: block 0
    float4 nxa = *(const float4*)xbase;
    float4 nxb = *(const float4*)(xbase + 4);

    // ================= Phase 1: priors -> registers =================
    #pragma unroll
    for (int s = 0; s < NBLKS; ++s) {
        const int bi = s % NBUF;

        const float4 xa = nxa, xb = nxb;
        // prefetch next block's x BEFORE the barrier wait (b fixed: cheap)
        if (s + 1 < NBLKS) {
            const float* xp = xbase + (size_t)(s + 1) * RPB * 8;
            nxa = *(const float4*)xp;
            nxb = *(const float4*)(xp + 4);
        }

        mbar_wait(mb0 + bi * 8, (s / NBUF) & 1);

        const float xv[8] = {xa.x, xa.y, xa.z, xa.w, xb.x, xb.y, xb.z, xb.w};
        #pragma unroll
        for (int o = 0; o < 8; ++o) P[s][o] = 0.f;

        const char* bufp = smc + (size_t)bi * BUFB + rowoff;
        #pragma unroll
        for (int i = 0; i < 8; ++i) {
            const float xvi = xv[i];
            #pragma unroll
            for (int m = 0; m < 2; ++m) {
                const int C = i * 4 + m;                 // 16B unit (oh=0 base)
                const uint32_t u = (uint32_t)((C & 7) + oh2);
                const uint32_t off = (uint32_t)((C >> 3) * COLW)
                                   + ((u ^ (uint32_t)r7) << 4);
                const float4 wv = *(const float4*)(bufp + off);
                P[s][m*4+0] = fmaf(xvi, wv.x, P[s][m*4+0]);
                P[s][m*4+1] = fmaf(xvi, wv.y, P[s][m*4+1]);
                P[s][m*4+2] = fmaf(xvi, wv.z, P[s][m*4+2]);
                P[s][m*4+3] = fmaf(xvi, wv.w, P[s][m*4+3]);
            }
        }

        __syncthreads();                     // all done reading buffer bi
        if (tid == 0 && s + NBUF < NBLKS) stage(s + NBUF);
    }

    // ================= Phase 2: routing =================
    // Row reduction within warp: shfl_xor 4,8,16 (preserve g,oh).
    // o-half join: shfl_xor 2 (preserve g).
    float Lr[NBLKS];

    // ---- iteration 0: s = mean_n priors ----
    {
        float acc[8];
        #pragma unroll
        for (int o = 0; o < 8; ++o) {
            float a = 0.f;
            #pragma unroll
            for (int k = 0; k < NBLKS; ++k) a += P[k][o];
            acc[o] = a;
        }
        #pragma unroll
        for (int off = 4; off <= 16; off <<= 1)
            #pragma unroll
            for (int o = 0; o < 8; ++o)
                acc[o] += __shfl_xor_sync(0xffffffffu, acc[o], off);
        if (lane < 4) {
            #pragma unroll
            for (int o = 0; o < 8; ++o)
                wred[(wid * 2 + g) * 16 + oh * 8 + o] = acc[o];
        }
        __syncthreads();
        if (tid < 32) {
            const int g2 = tid & 1, o2 = tid >> 1;
            float sv = 0.f;
            #pragma unroll
            for (int wi = 0; wi < NWARPS; ++wi)
                sv += wred[(wi * 2 + g2) * 16 + o2];
            sv *= (1.0f / Nn);
            float sq = sv * sv;
            #pragma unroll
            for (int off = 2; off <= 16; off <<= 1)
                sq += __shfl_xor_sync(0xffffffffu, sq, off);
            const float coef = sq / (1.f + sq) * rsqrtf(sq);
            outv[g2 * 16 + o2] = sv * coef;
        }
        __syncthreads();
    }

    // ---- iterations 1 and 2 ----
    #pragma unroll
    for (int it = 1; it < 3; ++it) {
        float ovr[8];
        #pragma unroll
        for (int o = 0; o < 8; ++o) ovr[o] = outv[g * 16 + oh * 8 + o];

        float lmax = -1e30f;
        #pragma unroll
        for (int k = 0; k < NBLKS; ++k) {
            float dot = 0.f;
            #pragma unroll
            for (int o = 0; o < 8; ++o) dot = fmaf(P[k][o], ovr[o], dot);
            dot += __shfl_xor_sync(0xffffffffu, dot, 2);   // join o-halves
            const float L = (it == 1) ? dot : (Lr[k] + dot);
            Lr[k] = L;
            lmax = fmaxf(lmax, L);
        }
        #pragma unroll
        for (int off = 4; off <= 16; off <<= 1)
            lmax = fmaxf(lmax, __shfl_xor_sync(0xffffffffu, lmax, off));
        __syncthreads();                 // previous sred consumers done
        if (lane < 2) sred[wid * 2 + g] = lmax;
        __syncthreads();
        float M = -1e30f;
        #pragma unroll
        for (int wi = 0; wi < NWARPS; ++wi)
            M = fmaxf(M, sred[wi * 2 + g]);

        float e[NBLKS], lsum = 0.f;
        #pragma unroll
        for (int k = 0; k < NBLKS; ++k) {
            e[k] = __expf(Lr[k] - M);
            lsum += e[k];
        }
        #pragma unroll
        for (int off = 4; off <= 16; off <<= 1)
            lsum += __shfl_xor_sync(0xffffffffu, lsum, off);
        __syncthreads();                 // all M reads done
        if (lane < 2) sred[wid * 2 + g] = lsum;
        __syncthreads();
        float Z = 0.f;
        #pragma unroll
        for (int wi = 0; wi < NWARPS; ++wi)
            Z += sred[wi * 2 + g];

        float acc[8];
        #pragma unroll
        for (int o = 0; o < 8; ++o) {
            float a = 0.f;
            #pragma unroll
            for (int k = 0; k < NBLKS; ++k) a = fmaf(e[k], P[k][o], a);
            acc[o] = a;
        }
        #pragma unroll
        for (int off = 4; off <= 16; off <<= 1)
            #pragma unroll
            for (int o = 0; o < 8; ++o)
                acc[o] += __shfl_xor_sync(0xffffffffu, acc[o], off);
        if (lane < 4) {
            #pragma unroll
            for (int o = 0; o < 8; ++o)
                wred[(wid * 2 + g) * 16 + oh * 8 + o] = acc[o];
        }
        __syncthreads();
        if (tid < 32) {
            const int g2 = tid & 1, o2 = tid >> 1;
            float sv = 0.f;
            #pragma unroll
            for (int wi = 0; wi < NWARPS; ++wi)
                sv += wred[(wi * 2 + g2) * 16 + o2];
            sv /= Z;
            float sq = sv * sv;
            #pragma unroll
            for (int off = 2; off <= 16; off <<= 1)
                sq += __shfl_xor_sync(0xffffffffu, sq, off);
            const float coef = sq / (1.f + sq) * rsqrtf(sq);
            outv[g2 * 16 + o2] = sv * coef;
        }
        __syncthreads();
    }

    // ================= output: [C, B, 1, 1, 16] =================
    if (tid < 32) {
        const int g2 = tid & 1, o2 = tid >> 1;
        out[((size_t)c * Bb + bbase + g2) * 16 + o2] = outv[g2 * 16 + o2];
    }
}

// ---------------- host ----------------
typedef CUresult (*EncodeTiledFn)(
    CUtensorMap*, CUtensorMapDataType, cuuint32_t, void*,
    const cuuint64_t*, const cuuint64_t*, const cuuint32_t*, const cuuint32_t*,
    CUtensorMapInterleave, CUtensorMapSwizzle, CUtensorMapL2promotion,
    CUtensorMapFloatOOBfill);

extern "C" void kernel_launch(void* const* d_in, const int* in_sizes, int n_in,
                              void* d_out, int out_size)
{
    const float* x = (const float*)d_in[0];
    void* w = (void*)d_in[1];
    float* out = (float*)d_out;

    EncodeTiledFn encode = nullptr;
    cudaDriverEntryPointQueryResult qr;
    cudaGetDriverEntryPoint("cuTensorMapEncodeTiled", (void**)&encode,
                            cudaEnableDefault, &qr);

    CUtensorMap tmap;
    cuuint64_t dims[2]    = { 128, (cuuint64_t)Cc * Nn };
    cuuint64_t strides[1] = { 128 * 4 };
    cuuint32_t box[2]     = { 32, RPB };
    cuuint32_t estr[2]    = { 1, 1 };
    encode(&tmap, CU_TENSOR_MAP_DATA_TYPE_FLOAT32, 2, w,
           dims, strides, box, estr,
           CU_TENSOR_MAP_INTERLEAVE_NONE, CU_TENSOR_MAP_SWIZZLE_128B,
           CU_TENSOR_MAP_L2_PROMOTION_L2_128B,
           CU_TENSOR_MAP_FLOAT_OOB_FILL_NONE);

    cudaFuncSetAttribute(capsule_kernel,
                         cudaFuncAttributeMaxDynamicSharedMemorySize, SMEM_BYTES);

    const int grid = Cc * (Bb / 2);   // 1280 CTAs
    capsule_kernel<<<grid, NTHREADS, SMEM_BYTES>>>(tmap, x, out);
}

// round 13
// speedup vs baseline: 1.1805x; 1.0586x over previous
#include <cuda_runtime.h>
#include <cuda.h>
#include <cstdint>

// CapsuleLayer dynamic routing — TMA (SW128) triple-buffered w staging with
// full/empty mbarrier pipeline (no per-block __syncthreads).
// x: [B=256, N=1152, CI=8] f32, w: [C=10, N=1152, CI=8, CO=16] f32
// out: [C, B, 1, 1, 16] f32
//
// One CTA = (c, pair of b). 576 threads; g=tid&1 (which b), oh=(tid>>1)&1
// (CO half), rw=tid>>2 (row 0..143). w[c] streams in 8 blocks of 144 rows;
// each block = 4 TMA 2D loads (box 32 floats x 144 rows, SW128) into 3
// round-robin buffers. full[bi]: tx mbarrier; empty[bi]: arrive-count-576
// mbarrier. Consumers arrive on empty and free-run to the next full wait;
// only tid0 blocks on empty before re-staging. Priors P[8][8] stay
// register-resident through all 3 routing iterations.

#define Cc 10
#define Bb 256
#define Nn 1152
#define NTHREADS 576
#define NWARPS 18
#define NBLKS 8
#define RPB 144
#define NBUF 3
#define COLW  18432              // bytes per 128B-column box (144*128)
#define BUFB  (4*COLW)           // 73728 bytes per buffer
#define MBAR_OFF (NBUF*BUFB)     // 221184 (full[3] then empty[3])
#define WRED_OFF (MBAR_OFF + 64)
#define SRED_OFF (WRED_OFF + NWARPS*2*16*4)
#define OUTV_OFF (SRED_OFF + NWARPS*2*4)
#define SMEM_BYTES (OUTV_OFF + 2*16*4)

__device__ __forceinline__ void mbar_init(uint32_t a, uint32_t cnt) {
    asm volatile("mbarrier.init.shared.b64 [%0], %1;" :: "r"(a), "r"(cnt) : "memory");
}
__device__ __forceinline__ void mbar_expect_tx(uint32_t a, uint32_t bytes) {
    asm volatile("mbarrier.arrive.expect_tx.shared.b64 _, [%0], %1;"
                 :: "r"(a), "r"(bytes) : "memory");
}
__device__ __forceinline__ void mbar_arrive(uint32_t a) {
    asm volatile("mbarrier.arrive.shared.b64 _, [%0];" :: "r"(a) : "memory");
}
__device__ __forceinline__ void mbar_wait(uint32_t a, uint32_t parity) {
    asm volatile(
        "{\n\t.reg .pred P1;\n\t"
        "W_%=:\n\t"
        "mbarrier.try_wait.parity.acquire.cta.shared::cta.b64 P1, [%0], %1, 0x989680;\n\t"
        "@P1 bra.uni D_%=;\n\t"
        "bra.uni W_%=;\n\t"
        "D_%=:\n\t}"
        :: "r"(a), "r"(parity) : "memory");
}
__device__ __forceinline__ void tma2d(uint32_t dst, const CUtensorMap* m,
                                      int cx, int cy, uint32_t mb) {
    asm volatile(
        "cp.async.bulk.tensor.2d.shared::cta.global.tile.mbarrier::complete_tx::bytes "
        "[%0], [%1, {%2, %3}], [%4];"
        :: "r"(dst), "l"(m), "r"(cx), "r"(cy), "r"(mb) : "memory");
}

__global__ __launch_bounds__(NTHREADS, 1)
void capsule_kernel(const __grid_constant__ CUtensorMap tmap,
                    const float* __restrict__ x,
                    float* __restrict__ out)
{
    extern __shared__ char smc[];
    float* wred = (float*)(smc + WRED_OFF);    // [18][2][16]
    float* sred = (float*)(smc + SRED_OFF);    // [18][2]
    float* outv = (float*)(smc + OUTV_OFF);    // [2][16]

    const int tid  = threadIdx.x;
    const int g    = tid & 1;               // which b of pair
    const int oh   = (tid >> 1) & 1;        // which CO half
    const int rw   = tid >> 2;              // row within block, 0..143
    const int lane = tid & 31;
    const int wid  = tid >> 5;
    const int c    = blockIdx.x >> 7;
    const int bbase = (blockIdx.x & 127) << 1;
    const int b    = bbase + g;

    const uint32_t sbase = (uint32_t)__cvta_generic_to_shared(smc);
    const uint32_t full0  = sbase + MBAR_OFF;        // full[bi]  = full0 + bi*8
    const uint32_t empty0 = sbase + MBAR_OFF + 24;   // empty[bi] = empty0 + bi*8

    auto stage = [&](int q) {               // tid 0 only
        const int bi = q % NBUF;
        const uint32_t dstb = sbase + (uint32_t)(bi * BUFB);
        const int cy = c * Nn + q * RPB;
        mbar_expect_tx(full0 + bi * 8, BUFB);
        #pragma unroll
        for (int j = 0; j < 4; ++j)
            tma2d(dstb + j * COLW, &tmap, j * 32, cy, full0 + bi * 8);
    };

    if (tid == 0) {
        #pragma unroll
        for (int bi = 0; bi < NBUF; ++bi) {
            mbar_init(full0  + bi * 8, 1);
            mbar_init(empty0 + bi * 8, NTHREADS);
        }
    }
    __syncthreads();
    if (tid == 0) { stage(0); stage(1); stage(2); }

    float P[NBLKS][8];
    const int r7  = rw & 7;
    const int oh2 = oh * 2;
    const uint32_t rowoff = (uint32_t)rw * 128;
    const float* __restrict__ xbase = x + ((size_t)b * Nn + rw) * 8;

    // initial x prefetch: block 0
    float4 nxa = *(const float4*)xbase;
    float4 nxb = *(const float4*)(xbase + 4);

    // ================= Phase 1: priors -> registers =================
    #pragma unroll
    for (int s = 0; s < NBLKS; ++s) {
        const int bi = s % NBUF;

        const float4 xa = nxa, xb = nxb;
        // prefetch next block's x BEFORE the full wait (b fixed: cheap)
        if (s + 1 < NBLKS) {
            const float* xp = xbase + (size_t)(s + 1) * RPB * 8;
            nxa = *(const float4*)xp;
            nxb = *(const float4*)(xp + 4);
        }

        mbar_wait(full0 + bi * 8, (s / NBUF) & 1);   // data resident

        const float xv[8] = {xa.x, xa.y, xa.z, xa.w, xb.x, xb.y, xb.z, xb.w};
        #pragma unroll
        for (int o = 0; o < 8; ++o) P[s][o] = 0.f;

        const char* bufp = smc + (size_t)bi * BUFB + rowoff;
        #pragma unroll
        for (int i = 0; i < 8; ++i) {
            const float xvi = xv[i];
            #pragma unroll
            for (int m = 0; m < 2; ++m) {
                const int C = i * 4 + m;                 // 16B unit (oh=0 base)
                const uint32_t u = (uint32_t)((C & 7) + oh2);
                const uint32_t off = (uint32_t)((C >> 3) * COLW)
                                   + ((u ^ (uint32_t)r7) << 4);
                const float4 wv = *(const float4*)(bufp + off);
                P[s][m*4+0] = fmaf(xvi, wv.x, P[s][m*4+0]);
                P[s][m*4+1] = fmaf(xvi, wv.y, P[s][m*4+1]);
                P[s][m*4+2] = fmaf(xvi, wv.z, P[s][m*4+2]);
                P[s][m*4+3] = fmaf(xvi, wv.w, P[s][m*4+3]);
            }
        }

        mbar_arrive(empty0 + bi * 8);        // done reading buffer bi

        if (tid == 0 && s + NBUF < NBLKS) {
            // wait until ALL threads released buffer bi, then refill it
            mbar_wait(empty0 + bi * 8, (s / NBUF) & 1);
            stage(s + NBUF);
        }
    }

    __syncthreads();      // converge before phase 2 (wred/sred reuse)

    // ================= Phase 2: routing =================
    // Row reduction within warp: shfl_xor 4,8,16 (preserve g,oh).
    // o-half join: shfl_xor 2 (preserve g).
    float Lr[NBLKS];

    // ---- iteration 0: s = mean_n priors ----
    {
        float acc[8];
        #pragma unroll
        for (int o = 0; o < 8; ++o) {
            float a = 0.f;
            #pragma unroll
            for (int k = 0; k < NBLKS; ++k) a += P[k][o];
            acc[o] = a;
        }
        #pragma unroll
        for (int off = 4; off <= 16; off <<= 1)
            #pragma unroll
            for (int o = 0; o < 8; ++o)
                acc[o] += __shfl_xor_sync(0xffffffffu, acc[o], off);
        if (lane < 4) {
            #pragma unroll
            for (int o = 0; o < 8; ++o)
                wred[(wid * 2 + g) * 16 + oh * 8 + o] = acc[o];
        }
        __syncthreads();
        if (tid < 32) {
            const int g2 = tid & 1, o2 = tid >> 1;
            float sv = 0.f;
            #pragma unroll
            for (int wi = 0; wi < NWARPS; ++wi)
                sv += wred[(wi * 2 + g2) * 16 + o2];
            sv *= (1.0f / Nn);
            float sq = sv * sv;
            #pragma unroll
            for (int off = 2; off <= 16; off <<= 1)
                sq += __shfl_xor_sync(0xffffffffu, sq, off);
            const float coef = sq / (1.f + sq) * rsqrtf(sq);
            outv[g2 * 16 + o2] = sv * coef;
        }
        __syncthreads();
    }

    // ---- iterations 1 and 2 ----
    #pragma unroll
    for (int it = 1; it < 3; ++it) {
        float ovr[8];
        #pragma unroll
        for (int o = 0; o < 8; ++o) ovr[o] = outv[g * 16 + oh * 8 + o];

        float lmax = -1e30f;
        #pragma unroll
        for (int k = 0; k < NBLKS; ++k) {
            float dot = 0.f;
            #pragma unroll
            for (int o = 0; o < 8; ++o) dot = fmaf(P[k][o], ovr[o], dot);
            dot += __shfl_xor_sync(0xffffffffu, dot, 2);   // join o-halves
            const float L = (it == 1) ? dot : (Lr[k] + dot);
            Lr[k] = L;
            lmax = fmaxf(lmax, L);
        }
        #pragma unroll
        for (int off = 4; off <= 16; off <<= 1)
            lmax = fmaxf(lmax, __shfl_xor_sync(0xffffffffu, lmax, off));
        __syncthreads();                 // previous sred consumers done
        if (lane < 2) sred[wid * 2 + g] = lmax;
        __syncthreads();
        float M = -1e30f;
        #pragma unroll
        for (int wi = 0; wi < NWARPS; ++wi)
            M = fmaxf(M, sred[wi * 2 + g]);

        float e[NBLKS], lsum = 0.f;
        #pragma unroll
        for (int k = 0; k < NBLKS; ++k) {
            e[k] = __expf(Lr[k] - M);
            lsum += e[k];
        }
        #pragma unroll
        for (int off = 4; off <= 16; off <<= 1)
            lsum += __shfl_xor_sync(0xffffffffu, lsum, off);
        __syncthreads();                 // all M reads done
        if (lane < 2) sred[wid * 2 + g] = lsum;
        __syncthreads();
        float Z = 0.f;
        #pragma unroll
        for (int wi = 0; wi < NWARPS; ++wi)
            Z += sred[wi * 2 + g];

        float acc[8];
        #pragma unroll
        for (int o = 0; o < 8; ++o) {
            float a = 0.f;
            #pragma unroll
            for (int k = 0; k < NBLKS; ++k) a = fmaf(e[k], P[k][o], a);
            acc[o] = a;
        }
        #pragma unroll
        for (int off = 4; off <= 16; off <<= 1)
            #pragma unroll
            for (int o = 0; o < 8; ++o)
                acc[o] += __shfl_xor_sync(0xffffffffu, acc[o], off);
        if (lane < 4) {
            #pragma unroll
            for (int o = 0; o < 8; ++o)
                wred[(wid * 2 + g) * 16 + oh * 8 + o] = acc[o];
        }
        __syncthreads();
        if (tid < 32) {
            const int g2 = tid & 1, o2 = tid >> 1;
            float sv = 0.f;
            #pragma unroll
            for (int wi = 0; wi < NWARPS; ++wi)
                sv += wred[(wi * 2 + g2) * 16 + o2];
            sv /= Z;
            float sq = sv * sv;
            #pragma unroll
            for (int off = 2; off <= 16; off <<= 1)
                sq += __shfl_xor_sync(0xffffffffu, sq, off);
            const float coef = sq / (1.f + sq) * rsqrtf(sq);
            outv[g2 * 16 + o2] = sv * coef;
        }
        __syncthreads();
    }

    // ================= output: [C, B, 1, 1, 16] =================
    if (tid < 32) {
        const int g2 = tid & 1, o2 = tid >> 1;
        out[((size_t)c * Bb + bbase + g2) * 16 + o2] = outv[g2 * 16 + o2];
    }
}

// ---------------- host ----------------
typedef CUresult (*EncodeTiledFn)(
    CUtensorMap*, CUtensorMapDataType, cuuint32_t, void*,
    const cuuint64_t*, const cuuint64_t*, const cuuint32_t*, const cuuint32_t*,
    CUtensorMapInterleave, CUtensorMapSwizzle, CUtensorMapL2promotion,
    CUtensorMapFloatOOBfill);

extern "C" void kernel_launch(void* const* d_in, const int* in_sizes, int n_in,
                              void* d_out, int out_size)
{
    const float* x = (const float*)d_in[0];
    void* w = (void*)d_in[1];
    float* out = (float*)d_out;

    EncodeTiledFn encode = nullptr;
    cudaDriverEntryPointQueryResult qr;
    cudaGetDriverEntryPoint("cuTensorMapEncodeTiled", (void**)&encode,
                            cudaEnableDefault, &qr);

    CUtensorMap tmap;
    cuuint64_t dims[2]    = { 128, (cuuint64_t)Cc * Nn };
    cuuint64_t strides[1] = { 128 * 4 };
    cuuint32_t box[2]     = { 32, RPB };
    cuuint32_t estr[2]    = { 1, 1 };
    encode(&tmap, CU_TENSOR_MAP_DATA_TYPE_FLOAT32, 2, w,
           dims, strides, box, estr,
           CU_TENSOR_MAP_INTERLEAVE_NONE, CU_TENSOR_MAP_SWIZZLE_128B,
           CU_TENSOR_MAP_L2_PROMOTION_L2_128B,
           CU_TENSOR_MAP_FLOAT_OOB_FILL_NONE);

    cudaFuncSetAttribute(capsule_kernel,
                         cudaFuncAttributeMaxDynamicSharedMemorySize, SMEM_BYTES);

    const int grid = Cc * (Bb / 2);   // 1280 CTAs
    capsule_kernel<<<grid, NTHREADS, SMEM_BYTES>>>(tmap, x, out);
}